// round 3
// baseline (speedup 1.0000x reference)
#include <cuda_runtime.h>
#include <cstdint>

#define N_NODES 100000
#define D_FEAT 48
#define V4 (D_FEAT / 4)          // 12 float4 chunks per node row
#define ROW_F4 (N_NODES * V4)    // float4s per node-feature buffer

// Ping-pong scratch (static device globals — no allocation allowed)
__device__ float4 g_buf0[ROW_F4];
__device__ float4 g_buf1[ROW_F4];

// ---------------------------------------------------------------------------
// Zero all three destination buffers in one pass (buf0, buf1, d_out).
// ---------------------------------------------------------------------------
__global__ void zero3_kernel(float4* __restrict__ out4) {
    unsigned i = blockIdx.x * blockDim.x + threadIdx.x;
    float4 z = make_float4(0.f, 0.f, 0.f, 0.f);
    if (i < ROW_F4) {
        g_buf0[i] = z;
        g_buf1[i] = z;
        out4[i]   = z;
    }
}

// ---------------------------------------------------------------------------
// One GCN layer: out[dst] += act(h[src]) for every edge.
// 12 threads per edge, each owning one 16-byte chunk of the 48-float row.
// Scatter via red.global.add.v4.f32 (no-return vector atomic, sm_90+).
// RELU of the *previous* layer is fused into the gather.
// ---------------------------------------------------------------------------
template <bool RELU_IN>
__global__ void gcn_layer_kernel(const float4* __restrict__ h,
                                 const int*    __restrict__ src,
                                 const int*    __restrict__ dst,
                                 float*        __restrict__ out,
                                 int n_edges) {
    unsigned tid = blockIdx.x * blockDim.x + threadIdx.x;
    unsigned e = tid / V4;
    unsigned c = tid - e * V4;
    if (e >= (unsigned)n_edges) return;

    int s = __ldg(src + e);
    int d = __ldg(dst + e);

    float4 v = __ldg(h + (unsigned)s * V4 + c);
    if (RELU_IN) {
        v.x = fmaxf(v.x, 0.f);
        v.y = fmaxf(v.y, 0.f);
        v.z = fmaxf(v.z, 0.f);
        v.w = fmaxf(v.w, 0.f);
    }

    float* dp = out + (unsigned)d * D_FEAT + c * 4;
    asm volatile("red.global.add.v4.f32 [%0], {%1, %2, %3, %4};"
                 :: "l"(dp), "f"(v.x), "f"(v.y), "f"(v.z), "f"(v.w)
                 : "memory");
}

extern "C" void kernel_launch(void* const* d_in, const int* in_sizes, int n_in,
                              void* d_out, int out_size) {
    const float4* features = (const float4*)d_in[0];   // [N_NODES, 48] fp32
    const int*    src      = (const int*)d_in[1];      // [E]
    const int*    dst      = (const int*)d_in[2];      // [E]
    float*        out      = (float*)d_out;            // [N_NODES, 48] fp32
    int n_edges = in_sizes[1];

    float4* buf0 = nullptr;
    float4* buf1 = nullptr;
    cudaGetSymbolAddress((void**)&buf0, g_buf0);
    cudaGetSymbolAddress((void**)&buf1, g_buf1);

    // Zero buf0, buf1, d_out in one kernel.
    {
        int threads = 256;
        int blocks = (ROW_F4 + threads - 1) / threads;
        zero3_kernel<<<blocks, threads>>>((float4*)d_out);
    }

    long long total = (long long)n_edges * V4;
    int threads = 256;
    int blocks = (int)((total + threads - 1) / threads);

    // Layer 0: out = scatter(features)
    gcn_layer_kernel<false><<<blocks, threads>>>(features, src, dst,
                                                 (float*)buf0, n_edges);
    // Layer 1: buf1 = scatter(relu(buf0))
    gcn_layer_kernel<true><<<blocks, threads>>>(buf0, src, dst,
                                                (float*)buf1, n_edges);
    // Layer 2: out = scatter(relu(buf1))  -- no final activation
    gcn_layer_kernel<true><<<blocks, threads>>>(buf1, src, dst,
                                                out, n_edges);
}

// round 4
// speedup vs baseline: 1.7222x; 1.7222x over previous
#include <cuda_runtime.h>
#include <cstdint>

#define N_NODES 100000
#define N_EDGES 1600000
#define D_FEAT 48
#define V4 (D_FEAT / 4)          // 12 float4 chunks per node row
#define ROW_F4 (N_NODES * V4)

#define SCAN_BS 512
#define SCAN_BLOCKS ((N_NODES + SCAN_BS - 1) / SCAN_BS)   // 196

#define NODES_PER_BLK 16
#define LAYER_THREADS (NODES_PER_BLK * V4)                // 192
#define EDGE_TILE 768                                     // smem idx staging (avg ~256/block)

// ---- static device scratch (no allocation allowed) ----
__device__ int    g_row[N_NODES + 1];     // degree -> row_ptr (in place)
__device__ int    g_cur[N_NODES];         // fill cursors
__device__ int    g_csr[N_EDGES];         // src node per dst-sorted edge
__device__ int    g_bsum[SCAN_BLOCKS];    // block sums for scan
__device__ float4 g_buf0[ROW_F4];
__device__ float4 g_buf1[ROW_F4];

// ---------------------------------------------------------------------------
// CSR build
// ---------------------------------------------------------------------------
__global__ void zero_deg_kernel() {
    int i = blockIdx.x * blockDim.x + threadIdx.x;
    if (i <= N_NODES) g_row[i] = 0;
}

__global__ void hist_kernel(const int* __restrict__ dst, int n_edges) {
    int e = blockIdx.x * blockDim.x + threadIdx.x;
    if (e < n_edges) atomicAdd(&g_row[dst[e]], 1);
}

// per-block reduction of degrees -> g_bsum
__global__ void scanA_kernel() {
    __shared__ int s[SCAN_BS];
    int t = threadIdx.x;
    int i = blockIdx.x * SCAN_BS + t;
    s[t] = (i < N_NODES) ? g_row[i] : 0;
    __syncthreads();
    for (int off = SCAN_BS / 2; off > 0; off >>= 1) {
        if (t < off) s[t] += s[t + off];
        __syncthreads();
    }
    if (t == 0) g_bsum[blockIdx.x] = s[0];
}

// exclusive scan of block sums (single block); also writes total to g_row[N]
__global__ void scanB_kernel() {
    __shared__ int s[SCAN_BLOCKS];
    int t = threadIdx.x;
    if (t < SCAN_BLOCKS) s[t] = g_bsum[t];
    __syncthreads();
    if (t == 0) {
        int run = 0;
        for (int b = 0; b < SCAN_BLOCKS; b++) {
            int v = s[b];
            s[b] = run;
            run += v;
        }
        g_row[N_NODES] = run;   // total edge count
    }
    __syncthreads();
    if (t < SCAN_BLOCKS) g_bsum[t] = s[t];
}

// local exclusive scan + block offset -> row_ptr (in g_row) and cursor copy
__global__ void scanC_kernel() {
    __shared__ int s[SCAN_BS];
    int t = threadIdx.x;
    int i = blockIdx.x * SCAN_BS + t;
    int v = (i < N_NODES) ? g_row[i] : 0;
    s[t] = v;
    __syncthreads();
    // Hillis-Steele inclusive scan
    for (int off = 1; off < SCAN_BS; off <<= 1) {
        int x = (t >= off) ? s[t - off] : 0;
        __syncthreads();
        s[t] += x;
        __syncthreads();
    }
    if (i < N_NODES) {
        int excl = g_bsum[blockIdx.x] + s[t] - v;
        g_row[i] = excl;
        g_cur[i] = excl;
    }
}

__global__ void fill_kernel(const int* __restrict__ src,
                            const int* __restrict__ dst, int n_edges) {
    int e = blockIdx.x * blockDim.x + threadIdx.x;
    if (e < n_edges) {
        int d = dst[e];
        int pos = atomicAdd(&g_cur[d], 1);
        g_csr[pos] = src[e];
    }
}

// ---------------------------------------------------------------------------
// One GCN layer (pull): out[n] = act( sum_{e in CSR[n]} h[src_e] )
// Block = 16 nodes x 12 chunk-threads. CSR indices staged through smem.
// ReLU applied on the STORE side (once per node, not once per edge-touch).
// ---------------------------------------------------------------------------
template <bool RELU_OUT>
__global__ void __launch_bounds__(LAYER_THREADS)
gcn_layer_kernel(const float4* __restrict__ h, float4* __restrict__ out) {
    __shared__ int s_idx[EDGE_TILE];

    int node0 = blockIdx.x * NODES_PER_BLK;
    int tid = threadIdx.x;
    int nl = tid / V4;
    int c  = tid - nl * V4;
    int node = node0 + nl;

    int lastn  = min(node0 + NODES_PER_BLK, N_NODES);
    int blkBeg = g_row[node0];
    int blkEnd = g_row[lastn];

    int beg = 0, end = 0;
    if (node < N_NODES) { beg = g_row[node]; end = g_row[node + 1]; }

    float4 acc = make_float4(0.f, 0.f, 0.f, 0.f);

    for (int base = blkBeg; base < blkEnd; base += EDGE_TILE) {
        int cnt = min(EDGE_TILE, blkEnd - base);
        __syncthreads();
        for (int i = tid; i < cnt; i += LAYER_THREADS)
            s_idx[i] = g_csr[base + i];
        __syncthreads();

        int lo = max(beg, base);
        int hi = min(end, base + cnt);
        #pragma unroll 4
        for (int j = lo; j < hi; ++j) {
            int s = s_idx[j - base];
            float4 v = __ldg(h + (unsigned)s * V4 + c);
            acc.x += v.x; acc.y += v.y; acc.z += v.z; acc.w += v.w;
        }
    }

    if (node < N_NODES) {
        if (RELU_OUT) {
            acc.x = fmaxf(acc.x, 0.f);
            acc.y = fmaxf(acc.y, 0.f);
            acc.z = fmaxf(acc.z, 0.f);
            acc.w = fmaxf(acc.w, 0.f);
        }
        out[(unsigned)node * V4 + c] = acc;
    }
}

extern "C" void kernel_launch(void* const* d_in, const int* in_sizes, int n_in,
                              void* d_out, int out_size) {
    const float4* features = (const float4*)d_in[0];   // [N, 48] fp32
    const int*    src      = (const int*)d_in[1];
    const int*    dst      = (const int*)d_in[2];
    float4*       out      = (float4*)d_out;
    int n_edges = in_sizes[1];

    float4* buf0 = nullptr;
    float4* buf1 = nullptr;
    cudaGetSymbolAddress((void**)&buf0, g_buf0);
    cudaGetSymbolAddress((void**)&buf1, g_buf1);

    int eblocks = (n_edges + 255) / 256;

    // ---- CSR build (once; reused by all 3 layers) ----
    zero_deg_kernel<<<(N_NODES + 256) / 256, 256>>>();
    hist_kernel<<<eblocks, 256>>>(dst, n_edges);
    scanA_kernel<<<SCAN_BLOCKS, SCAN_BS>>>();
    scanB_kernel<<<1, 256>>>();
    scanC_kernel<<<SCAN_BLOCKS, SCAN_BS>>>();
    fill_kernel<<<eblocks, 256>>>(src, dst, n_edges);

    // ---- 3 layers, pull-style ----
    int lblocks = (N_NODES + NODES_PER_BLK - 1) / NODES_PER_BLK;   // 6250
    gcn_layer_kernel<true ><<<lblocks, LAYER_THREADS>>>(features, buf0);
    gcn_layer_kernel<true ><<<lblocks, LAYER_THREADS>>>(buf0, buf1);
    gcn_layer_kernel<false><<<lblocks, LAYER_THREADS>>>(buf1, out);
}

// round 5
// speedup vs baseline: 1.8231x; 1.0586x over previous
#include <cuda_runtime.h>
#include <cuda_fp16.h>
#include <cstdint>

#define N_NODES 100000
#define N_EDGES 1600000
#define D_FEAT 48
#define ROW_F4 (N_NODES * 12)

#define SCAN_BS 512
#define SCAN_BLOCKS ((N_NODES + SCAN_BS - 1) / SCAN_BS)   // 196

// ---- static device scratch (no allocation allowed) ----
__device__ int   g_row[N_NODES + 1];
__device__ int   g_cur[N_NODES];
__device__ int   g_csr[N_EDGES];
__device__ int   g_bsum[SCAN_BLOCKS];
__device__ uint4 g_buf0[N_NODES * 6];    // half[N,48] = 96B/row = 6x16B
__device__ uint4 g_buf1[N_NODES * 6];

// ---------------------------------------------------------------------------
// CSR build
// ---------------------------------------------------------------------------
__global__ void zero_deg_kernel() {
    int i = blockIdx.x * blockDim.x + threadIdx.x;
    if (i <= N_NODES) g_row[i] = 0;
}

__global__ void hist_kernel(const int* __restrict__ dst, int n_edges) {
    int e = blockIdx.x * blockDim.x + threadIdx.x;
    if (e < n_edges) atomicAdd(&g_row[dst[e]], 1);
}

__global__ void scanA_kernel() {
    __shared__ int s[SCAN_BS];
    int t = threadIdx.x;
    int i = blockIdx.x * SCAN_BS + t;
    s[t] = (i < N_NODES) ? g_row[i] : 0;
    __syncthreads();
    for (int off = SCAN_BS / 2; off > 0; off >>= 1) {
        if (t < off) s[t] += s[t + off];
        __syncthreads();
    }
    if (t == 0) g_bsum[blockIdx.x] = s[0];
}

// parallel exclusive scan of the 196 block sums; writes total to g_row[N]
__global__ void scanB_kernel() {
    __shared__ int s[256];
    int t = threadIdx.x;
    int v = (t < SCAN_BLOCKS) ? g_bsum[t] : 0;
    s[t] = v;
    __syncthreads();
    for (int off = 1; off < 256; off <<= 1) {
        int x = (t >= off) ? s[t - off] : 0;
        __syncthreads();
        s[t] += x;
        __syncthreads();
    }
    if (t < SCAN_BLOCKS) g_bsum[t] = s[t] - v;   // exclusive
    if (t == 255) g_row[N_NODES] = s[255];       // total edges
}

__global__ void scanC_kernel() {
    __shared__ int s[SCAN_BS];
    int t = threadIdx.x;
    int i = blockIdx.x * SCAN_BS + t;
    int v = (i < N_NODES) ? g_row[i] : 0;
    s[t] = v;
    __syncthreads();
    for (int off = 1; off < SCAN_BS; off <<= 1) {
        int x = (t >= off) ? s[t - off] : 0;
        __syncthreads();
        s[t] += x;
        __syncthreads();
    }
    if (i < N_NODES) {
        int excl = g_bsum[blockIdx.x] + s[t] - v;
        g_row[i] = excl;
        g_cur[i] = excl;
    }
}

__global__ void fill_kernel(const int* __restrict__ src,
                            const int* __restrict__ dst, int n_edges) {
    int e = blockIdx.x * blockDim.x + threadIdx.x;
    if (e < n_edges) {
        int d = dst[e];
        int pos = atomicAdd(&g_cur[d], 1);
        g_csr[pos] = src[e];
    }
}

// ---------------------------------------------------------------------------
// Layer 1: fp32 features -> half buf (relu on store).
// 32 nodes/block x 12 chunk-threads (16B chunks of fp32 row).
// ---------------------------------------------------------------------------
#define L1_NODES 32
#define L1_THREADS (L1_NODES * 12)   // 384
#define L1_TILE 1024

__global__ void __launch_bounds__(L1_THREADS)
layer_f32_to_h(const float4* __restrict__ h, uint2* __restrict__ out) {
    __shared__ int s_idx[L1_TILE];
    int node0 = blockIdx.x * L1_NODES;
    int tid = threadIdx.x;
    int nl = tid / 12, c = tid - nl * 12;
    int node = node0 + nl;

    int lastn  = min(node0 + L1_NODES, N_NODES);
    int blkBeg = g_row[node0];
    int blkEnd = g_row[lastn];
    int beg = 0, end = 0;
    if (node < N_NODES) { beg = g_row[node]; end = g_row[node + 1]; }

    float4 acc = make_float4(0.f, 0.f, 0.f, 0.f);
    for (int base = blkBeg; base < blkEnd; base += L1_TILE) {
        int cnt = min(L1_TILE, blkEnd - base);
        __syncthreads();
        for (int i = tid; i < cnt; i += L1_THREADS)
            s_idx[i] = g_csr[base + i];
        __syncthreads();
        int lo = max(beg, base);
        int hi = min(end, base + cnt);
        #pragma unroll 4
        for (int j = lo; j < hi; ++j) {
            int s = s_idx[j - base];
            float4 v = __ldg(h + (unsigned)s * 12 + c);
            acc.x += v.x; acc.y += v.y; acc.z += v.z; acc.w += v.w;
        }
    }

    if (node < N_NODES) {
        __half2 a = __floats2half2_rn(fmaxf(acc.x, 0.f), fmaxf(acc.y, 0.f));
        __half2 b = __floats2half2_rn(fmaxf(acc.z, 0.f), fmaxf(acc.w, 0.f));
        uint2 u;
        u.x = *reinterpret_cast<unsigned*>(&a);
        u.y = *reinterpret_cast<unsigned*>(&b);
        out[(unsigned)node * 12 + c] = u;   // row = 12 x 8B = 96B
    }
}

// ---------------------------------------------------------------------------
// Layers 2/3: half buf in. FINAL=false -> half out + relu; FINAL=true -> fp32 out.
// 32 nodes/block x 6 chunk-threads (16B half chunks = 8 feats each).
// ---------------------------------------------------------------------------
#define LH_NODES 32
#define LH_THREADS (LH_NODES * 6)    // 192
#define LH_TILE 1024

template <bool FINAL>
__global__ void __launch_bounds__(LH_THREADS)
layer_h(const uint4* __restrict__ h, uint4* __restrict__ outh,
        float4* __restrict__ outf) {
    __shared__ int s_idx[LH_TILE];
    int node0 = blockIdx.x * LH_NODES;
    int tid = threadIdx.x;
    int nl = tid / 6, c = tid - nl * 6;
    int node = node0 + nl;

    int lastn  = min(node0 + LH_NODES, N_NODES);
    int blkBeg = g_row[node0];
    int blkEnd = g_row[lastn];
    int beg = 0, end = 0;
    if (node < N_NODES) { beg = g_row[node]; end = g_row[node + 1]; }

    float a0 = 0.f, a1 = 0.f, a2 = 0.f, a3 = 0.f;
    float a4 = 0.f, a5 = 0.f, a6 = 0.f, a7 = 0.f;

    for (int base = blkBeg; base < blkEnd; base += LH_TILE) {
        int cnt = min(LH_TILE, blkEnd - base);
        __syncthreads();
        for (int i = tid; i < cnt; i += LH_THREADS)
            s_idx[i] = g_csr[base + i];
        __syncthreads();
        int lo = max(beg, base);
        int hi = min(end, base + cnt);
        #pragma unroll 4
        for (int j = lo; j < hi; ++j) {
            int s = s_idx[j - base];
            uint4 u = __ldg(h + (unsigned)s * 6 + c);
            __half2 h0 = *reinterpret_cast<__half2*>(&u.x);
            __half2 h1 = *reinterpret_cast<__half2*>(&u.y);
            __half2 h2 = *reinterpret_cast<__half2*>(&u.z);
            __half2 h3 = *reinterpret_cast<__half2*>(&u.w);
            float2 f0 = __half22float2(h0);
            float2 f1 = __half22float2(h1);
            float2 f2 = __half22float2(h2);
            float2 f3 = __half22float2(h3);
            a0 += f0.x; a1 += f0.y; a2 += f1.x; a3 += f1.y;
            a4 += f2.x; a5 += f2.y; a6 += f3.x; a7 += f3.y;
        }
    }

    if (node < N_NODES) {
        if (FINAL) {
            // fp32 out, no activation: 2 x float4 per thread, row = 192B
            outf[(unsigned)node * 12 + c * 2]     = make_float4(a0, a1, a2, a3);
            outf[(unsigned)node * 12 + c * 2 + 1] = make_float4(a4, a5, a6, a7);
        } else {
            __half2 p0 = __floats2half2_rn(fmaxf(a0, 0.f), fmaxf(a1, 0.f));
            __half2 p1 = __floats2half2_rn(fmaxf(a2, 0.f), fmaxf(a3, 0.f));
            __half2 p2 = __floats2half2_rn(fmaxf(a4, 0.f), fmaxf(a5, 0.f));
            __half2 p3 = __floats2half2_rn(fmaxf(a6, 0.f), fmaxf(a7, 0.f));
            uint4 u;
            u.x = *reinterpret_cast<unsigned*>(&p0);
            u.y = *reinterpret_cast<unsigned*>(&p1);
            u.z = *reinterpret_cast<unsigned*>(&p2);
            u.w = *reinterpret_cast<unsigned*>(&p3);
            outh[(unsigned)node * 6 + c] = u;
        }
    }
}

extern "C" void kernel_launch(void* const* d_in, const int* in_sizes, int n_in,
                              void* d_out, int out_size) {
    const float4* features = (const float4*)d_in[0];
    const int*    src      = (const int*)d_in[1];
    const int*    dst      = (const int*)d_in[2];
    float4*       out      = (float4*)d_out;
    int n_edges = in_sizes[1];

    uint4* buf0 = nullptr;
    uint4* buf1 = nullptr;
    cudaGetSymbolAddress((void**)&buf0, g_buf0);
    cudaGetSymbolAddress((void**)&buf1, g_buf1);

    int eblocks = (n_edges + 255) / 256;

    // ---- CSR build ----
    zero_deg_kernel<<<(N_NODES + 256) / 256, 256>>>();
    hist_kernel<<<eblocks, 256>>>(dst, n_edges);
    scanA_kernel<<<SCAN_BLOCKS, SCAN_BS>>>();
    scanB_kernel<<<1, 256>>>();
    scanC_kernel<<<SCAN_BLOCKS, SCAN_BS>>>();
    fill_kernel<<<eblocks, 256>>>(src, dst, n_edges);

    // ---- 3 layers ----
    int b1 = (N_NODES + L1_NODES - 1) / L1_NODES;
    int bh = (N_NODES + LH_NODES - 1) / LH_NODES;
    layer_f32_to_h<<<b1, L1_THREADS>>>(features, (uint2*)buf0);
    layer_h<false><<<bh, LH_THREADS>>>(buf0, buf1, nullptr);
    layer_h<true ><<<bh, LH_THREADS>>>(buf1, nullptr, out);
}